// round 17
// baseline (speedup 1.0000x reference)
#include <cuda_runtime.h>

#define SEQ      784
#define BATCH    512
#define NTHREADS 128
#define SPB      2                     // sequences per block; each seq owned by a WARP PAIR
#define EP       8                     // packed pairs per lane (16 elems: (i, i+8))

typedef unsigned long long u64;

// ---- f32x2 packed helpers (sm_100+/sm_103a; FFMA2 reachable only via PTX) ----
__device__ __forceinline__ u64 pk(float lo, float hi) {
    u64 r; asm("mov.b64 %0, {%1, %2};" : "=l"(r) : "f"(lo), "f"(hi)); return r;
}
__device__ __forceinline__ void upk(u64 v, float& lo, float& hi) {
    asm("mov.b64 {%0, %1}, %2;" : "=f"(lo), "=f"(hi) : "l"(v));
}
__device__ __forceinline__ u64 fma2(u64 a, u64 b, u64 c) {
    u64 d; asm("fma.rn.f32x2 %0, %1, %2, %3;" : "=l"(d) : "l"(a), "l"(b), "l"(c)); return d;
}
__device__ __forceinline__ u64 mul2(u64 a, u64 b) {
    u64 d; asm("mul.rn.f32x2 %0, %1, %2;" : "=l"(d) : "l"(a), "l"(b)); return d;
}

// Quad tanh from pre-scaled args (xvK = (2/ln2)*xv), ONE rcp for 4 values:
//   tanh = 1 - 2/d, d = 2^xvK + 1;  rc = rcp(d0 d1 d2 d3), unwound by muls.
// Clamp xvK <= 30 -> product <= ~2^120 never overflows; tanh(10.4) is within
// 3e-9 of 1 so the clamp is numerically invisible. MUFU: 4 ex2 + 1 rcp.
__device__ __forceinline__ void tanh_quad(float x0, float x1, float x2, float x3,
                                          float& t0, float& t1, float& t2, float& t3) {
    float e0, e1, e2, e3, rc;
    x0 = fminf(x0, 30.f); x1 = fminf(x1, 30.f);
    x2 = fminf(x2, 30.f); x3 = fminf(x3, 30.f);
    asm("ex2.approx.ftz.f32 %0, %1;" : "=f"(e0) : "f"(x0));
    asm("ex2.approx.ftz.f32 %0, %1;" : "=f"(e1) : "f"(x1));
    asm("ex2.approx.ftz.f32 %0, %1;" : "=f"(e2) : "f"(x2));
    asm("ex2.approx.ftz.f32 %0, %1;" : "=f"(e3) : "f"(x3));
    const float d0 = e0 + 1.f, d1 = e1 + 1.f, d2 = e2 + 1.f, d3 = e3 + 1.f;
    const float p01 = d0 * d1, p23 = d2 * d3;
    asm("rcp.approx.ftz.f32 %0, %1;" : "=f"(rc) : "f"(p01 * p23));
    const float rA = rc * p23, rB = rc * p01;   // 1/(d0 d1), 1/(d2 d3)
    t0 = fmaf(-2.f, rA * d1, 1.f);
    t1 = fmaf(-2.f, rA * d0, 1.f);
    t2 = fmaf(-2.f, rB * d3, 1.f);
    t3 = fmaf(-2.f, rB * d2, 1.f);
}

// WARP-PAIR PER SEQUENCE: block = 128 thr = 4 warps = 2 sequences. Warp
// (seq, half) owns elems [half*512, half*512+512), 16/lane packed f32x2 as
// (i, i+8). Total warps chip-wide: 1024 -> 1.73/SMSP (vs 0.86 for R15/R16),
// restoring cross-warp latency hiding while keeping packed math.
// Cross-warp flow is ONE float per seq per step (lower half's warp total),
// parity-buffered; one __syncthreads serves both sequences.
//
// HiPPO bilinear step collapses (A diagonal + rank-1 semiseparable) to ONE
// linear scan over hidden index i:
//   r_{i+1} = alf_i r_i + w_i,  w_i = gam_i h_i + dlt_i u      (r_0 = 0)
//   xv_i    = A1_i h_i + gam_i (c u - (c/2) r_i) ;  h_i = tanh(xv_i)
// Time-invariant multiplicative scan coefficients -> 'a' ladder (saL, eaC)
// precomputed; per step the warp scan runs on 'b' only.
__global__ void __launch_bounds__(NTHREADS, 2)
ssm_scan_kernel(const float* __restrict__ x,
                const float* __restrict__ C,
                const float* __restrict__ W,
                const float* __restrict__ bias,
                float* __restrict__ out)
{
    __shared__ float xsv[SEQ][SPB];      // xsv[t][seq]
    __shared__ float wtb[2][SPB];        // lower-half warp totals, parity-buffered
    __shared__ float red[4];

    const int tid  = threadIdx.x;
    const int lane = tid & 31;
    const int wid  = tid >> 5;
    const int seq  = wid >> 1;           // 0/1: which sequence in the block
    const int half = wid & 1;            // 0: elems [0,512)  1: [512,1024)
    const int bidx = blockIdx.x;

    for (int i = tid; i < SPB * SEQ; i += NTHREADS) {
        const int s = i / SEQ, t = i - s * SEQ;
        xsv[t][s] = x[(bidx * SPB + s) * SEQ + t];
    }

    const float KT = 2.885390081777927f;  // 2/ln(2)

    // ---- per-lane constants in double (matches reference fp64 HiPPO).
    //      Lane covers q in [half*512 + 16*lane, +16), packed (i, i+8). ----
    u64 alf2[EP], gam2[EP], dlt2[EP], a1k2[EP], h2[EP], w2[EP];
    float A_lo = 1.f, A_hi = 1.f;
    u64 mc2K2;
    float cKT;
    {
        const double step = 1.0 / (double)SEQ;
        const double c    = 0.5 * step;
        cKT = (float)c * KT;
        const float m = (float)(-0.5 * c) * KT;
        mc2K2 = pk(m, m);
        const int qb = half * 512 + lane * 16;
        #pragma unroll
        for (int i = 0; i < EP; ++i) {
            const double q0 = (double)(qb + i);
            const double q1 = q0 + 8.0;
            const double P0 = sqrt(1.0 + 2.0 * q0), P1 = sqrt(1.0 + 2.0 * q1);
            const double D0 = 1.0 + c * (1.0 + q0), D1 = 1.0 + c * (1.0 + q1);
            const float a0 = (float)((1.0 - c * q0) / D0);
            const float a1 = (float)((1.0 - c * q1) / D1);
            alf2[i] = pk(a0, a1);
            gam2[i] = pk((float)(2.0 * P0 / D0), (float)(2.0 * P1 / D1));
            dlt2[i] = pk((float)(step * P0 * P0 / D0), (float)(step * P1 * P1 / D1));
            a1k2[i] = pk((float)((1.0 - c * (1.0 + q0)) / D0) * KT,
                         (float)((1.0 - c * (1.0 + q1)) / D1) * KT);
            h2[i] = 0ull;
            A_lo *= a0; A_hi *= a1;
        }
    }

    // ---- one-time 'a' ladder over lane totals (time-invariant) ----
    float saL[5];
    float sa = A_lo * A_hi;
    #pragma unroll
    for (int k = 0; k < 5; ++k) {
        saL[k] = sa;
        float ra = __shfl_up_sync(0xffffffffu, sa, 1 << k);
        if (lane >= (1 << k)) sa *= ra;
    }
    float eaC = __shfl_up_sync(0xffffffffu, sa, 1);
    if (lane == 0) eaC = 1.f;
    __syncthreads();                      // xs ready

    // =========================== main time loop ===========================
    #pragma unroll 2
    for (int t = 0; t < SEQ; ++t) {
        const float u = xsv[t][seq];      // warp-broadcast LDS
        const u64 u2 = pk(u, u);
        const float cuK = cKT * u;
        const u64 cuK2 = pk(cuK, cuK);

        // ---- w and packed serial b-chain (depth 8) ----
        u64 sb2 = 0ull;
        #pragma unroll
        for (int i = 0; i < EP; ++i) {
            w2[i] = fma2(gam2[i], h2[i], mul2(dlt2[i], u2));
            sb2   = fma2(alf2[i], sb2, w2[i]);
        }
        float cb_lo, cb_hi;
        upk(sb2, cb_lo, cb_hi);
        float tb = fmaf(A_hi, cb_lo, cb_hi);   // lane-total 'b' (16 elems)

        // ---- warp inclusive scan on 'b' ('a' ladder precomputed) ----
        float s = tb;
        #pragma unroll
        for (int k = 0; k < 5; ++k) {
            float rb = __shfl_up_sync(0xffffffffu, s, 1 << k);
            if (lane >= (1 << k)) s = fmaf(saL[k], rb, s);
        }
        float eb = __shfl_up_sync(0xffffffffu, s, 1);
        if (lane == 0) eb = 0.f;

        const int par = t & 1;                // constant under unroll 2
        if (half == 0 && lane == 31) wtb[par][seq] = s;  // lower warp total G0
        __syncthreads();                      // ONE barrier, both seqs advance

        // r entering this lane: half 0 -> eb; half 1 -> eaC*G0 + eb
        float r0 = half ? fmaf(eaC, wtb[par][seq], eb) : eb;
        float r8 = fmaf(A_lo, r0, cb_lo);     // r entering the hi sub-chain
        u64 r2 = pk(r0, r8);

        // ---- apply: packed r-chain; quad-rcp tanh over (lo_i,hi_i,lo_i+1,hi_i+1) ----
        #pragma unroll
        for (int i = 0; i < EP; i += 2) {
            u64 rhoA = fma2(mc2K2, r2, cuK2);
            u64 xvA  = fma2(gam2[i], rhoA, mul2(a1k2[i], h2[i]));
            r2 = fma2(alf2[i], r2, w2[i]);
            u64 rhoB = fma2(mc2K2, r2, cuK2);
            u64 xvB  = fma2(gam2[i + 1], rhoB, mul2(a1k2[i + 1], h2[i + 1]));
            r2 = fma2(alf2[i + 1], r2, w2[i + 1]);
            float x0, x1, x2, x3, t0, t1, t2, t3;
            upk(xvA, x0, x1); upk(xvB, x2, x3);
            tanh_quad(x0, x1, x2, x3, t0, t1, t2, t3);
            h2[i]     = pk(t0, t1);
            h2[i + 1] = pk(t2, t3);
        }
    }

    // ---- epilogue: y_s = C . h_s over warp-pair ; out = y*W + bias ----
    const int qb = half * 512 + lane * 16;
    float partial = 0.f;
    #pragma unroll
    for (int i = 0; i < EP; ++i) {
        float hl, hh;
        upk(h2[i], hl, hh);
        partial = fmaf(__ldg(&C[qb + i]),     hl, partial);
        partial = fmaf(__ldg(&C[qb + 8 + i]), hh, partial);
    }
    #pragma unroll
    for (int d = 16; d > 0; d >>= 1)
        partial += __shfl_down_sync(0xffffffffu, partial, d);
    if (lane == 0) red[wid] = partial;
    __syncthreads();
    if (tid < SPB) {
        float y = red[2 * tid] + red[2 * tid + 1];
        #pragma unroll
        for (int o = 0; o < 10; ++o)
            out[(bidx * SPB + tid) * 10 + o] = fmaf(y, W[o], bias[o]);
    }
}

extern "C" void kernel_launch(void* const* d_in, const int* in_sizes, int n_in,
                              void* d_out, int out_size) {
    const float* x    = (const float*)d_in[0];   // (512, 784, 1)
    const float* C    = (const float*)d_in[1];   // (1, 1024)
    const float* W    = (const float*)d_in[2];   // (1, 10)
    const float* bias = (const float*)d_in[3];   // (10,)
    float* out        = (float*)d_out;           // (512, 10)
    ssm_scan_kernel<<<BATCH / SPB, NTHREADS>>>(x, C, W, bias, out);
}